// round 5
// baseline (speedup 1.0000x reference)
#include <cuda_runtime.h>
#include <cuda_bf16.h>
#include <math.h>
#include <stdint.h>

#define B_  2
#define T_  2048
#define C_  1024
#define H_  16
#define HD  64
#define BT  (B_*T_)      // 4096
#define C5  (5*C_)       // 5120
#define NC  (T_/HD)      // 32 chunks
#define BH  (B_*H_)      // 32

// ---------------- scratch (device globals) ----------------
__device__ float g_qkvff[BT*(size_t)C5];          // q,k,v fp32 (cols < 3C used)
__device__ float g_W [BH*(size_t)NC*HD*HD];
__device__ float g_S [BH*(size_t)NC*HD*HD];
__device__ float g_y [BT*(size_t)C_];             // GN'd attention out
__device__ float g_yp[BT*(size_t)C_];             // proj out
// split-bf16 operands, layout [hi | lo] along K' = 2K
__device__ __nv_bfloat16 g_a_qkv [BT*(size_t)2*C_];
__device__ __nv_bfloat16 g_b_qkv [C5*(size_t)2*C_];
__device__ __nv_bfloat16 g_a_x   [BT*(size_t)2*C_];
__device__ __nv_bfloat16 g_b_gat [C_*(size_t)2*C_];
__device__ __nv_bfloat16 g_a_prj [BT*(size_t)2*C_];
__device__ __nv_bfloat16 g_b_prj [C_*(size_t)2*C_];
__device__ __nv_bfloat16 g_a_ff  [BT*(size_t)4*C_];   // gelu(ff) split, K=2048
__device__ __nv_bfloat16 g_b_ff  [C_*(size_t)4*C_];

// ---------------- PTX helpers ----------------
__device__ __forceinline__ uint32_t smem_u32(const void* p) {
    uint32_t a;
    asm("{ .reg .u64 t; cvta.to.shared.u64 t, %1; cvt.u32.u64 %0, t; }" : "=r"(a) : "l"(p));
    return a;
}
#define CPA(dst, src)  asm volatile("cp.async.cg.shared.global [%0], [%1], 16;" :: "r"(dst), "l"(src) : "memory")
#define CPC()          asm volatile("cp.async.commit_group;" ::: "memory")
#define CPW(n)         asm volatile("cp.async.wait_group %0;" :: "n"(n) : "memory")
#define SWZ64(o) ((o) ^ (((o) >> 3) & 0x30))

#define LDM_X4(r0, r1, r2, r3, a) \
    asm volatile("ldmatrix.sync.aligned.m8n8.x4.shared.b16 {%0,%1,%2,%3}, [%4];" \
        : "=r"(r0), "=r"(r1), "=r"(r2), "=r"(r3) : "r"(a))

#define MMA_BF16(d, a0, a1, a2, a3, b0, b1) \
    asm volatile("mma.sync.aligned.m16n8k16.row.col.f32.bf16.bf16.f32 " \
        "{%0,%1,%2,%3}, {%4,%5,%6,%7}, {%8,%9}, {%0,%1,%2,%3};" \
        : "+f"((d)[0]), "+f"((d)[1]), "+f"((d)[2]), "+f"((d)[3]) \
        : "r"(a0), "r"(a1), "r"(a2), "r"(a3), "r"(b0), "r"(b1))

// ---------------- warp-MMA split-bf16 NT GEMM, fragment-reuse 3-term scheme ----------------
// C[M, N] = A[M, K]*B[N, K]^T in fp32-compensated bf16:
//   acc = Ah.Bh + Al.Bh + Ah.Bl   (A, B stored [hi|lo], row stride 2K)
// block tile 128x256, BK=32, S=3 cp.async stages, 8 warps (2m x 4n), warp 64x64
// EPI 0 (qkvff): n<3072 -> fp32 Cout ; n>=3072 -> gelu+split into osplit (stride 4096)
// EPI 1: silu(v+bias[n])*aux0 -> split osplit (stride 2048)
// EPI 2: v+bias[n] -> Cout     EPI 3: v+aux0+aux1 -> Cout
template<int EPI>
__global__ void __launch_bounds__(256, 1) mma_gemm(
    const __nv_bfloat16* __restrict__ A, const __nv_bfloat16* __restrict__ Bm,
    int K, int N, float* __restrict__ Cout,
    const float* __restrict__ bias, const float* __restrict__ aux0,
    const float* __restrict__ aux1, __nv_bfloat16* __restrict__ osplit)
{
    extern __shared__ __align__(1024) char smem_raw[];
    const int S = 3;
    const uint32_t STAGE = 49152;   // A_hi 8K | A_lo 8K | B_hi 16K | B_lo 16K
    uint32_t sbase = (smem_u32(smem_raw) + 1023) & ~1023u;

    int tid = threadIdx.x;
    int wid = tid >> 5, lane = tid & 31;
    int warp_m = wid & 1, warp_n = wid >> 1;
    int bm = blockIdx.y << 7, bn = blockIdx.x << 8;
    int K2 = 2 * K;
    const int nk = K >> 5;

    auto load_stage = [&](int s, int k) {
        uint32_t st = sbase + (uint32_t)s * STAGE;
        const __nv_bfloat16* Ag = A + (size_t)bm * K2 + (size_t)k * 32;
        const __nv_bfloat16* Bg = Bm + (size_t)bn * K2 + (size_t)k * 32;
        #pragma unroll
        for (int q = 0; q < 2; q++) {
            int i = tid + (q << 8);
            int r = i >> 2, c = i & 3;
            uint32_t off = SWZ64(r * 64 + c * 16);
            const __nv_bfloat16* src = Ag + (size_t)r * K2 + c * 8;
            CPA(st + off,        (const char*)src);
            CPA(st + 8192 + off, (const char*)(src + K));
        }
        #pragma unroll
        for (int q = 0; q < 4; q++) {
            int i = tid + (q << 8);
            int r = i >> 2, c = i & 3;
            uint32_t off = SWZ64(r * 64 + c * 16);
            const __nv_bfloat16* src = Bg + (size_t)r * K2 + c * 8;
            CPA(st + 16384 + off, (const char*)src);
            CPA(st + 32768 + off, (const char*)(src + K));
        }
    };

    float acc[4][8][4];
    #pragma unroll
    for (int mt = 0; mt < 4; mt++)
        #pragma unroll
        for (int nt = 0; nt < 8; nt++)
            #pragma unroll
            for (int u = 0; u < 4; u++) acc[mt][nt][u] = 0.f;

    int j = lane >> 3;
    int lrow = lane & 7;
    int a_row_off = ((j & 1) << 3) + lrow;
    int a_byte_off = (j >> 1) << 4;
    int b_row_off = ((j >> 1) << 3) + lrow;
    int b_byte_off = (j & 1) << 4;

    #pragma unroll
    for (int p = 0; p < S - 1; p++) { load_stage(p, p); CPC(); }

    for (int k = 0; k < nk; k++) {
        CPW(S - 2);
        __syncthreads();
        if (k + S - 1 < nk) load_stage((k + S - 1) % S, k + S - 1);
        CPC();

        uint32_t st = sbase + (uint32_t)(k % S) * STAGE;
        #pragma unroll
        for (int ks = 0; ks < 2; ks++) {
            uint32_t ah[4][4], al[4][4];
            #pragma unroll
            for (int mt = 0; mt < 4; mt++) {
                int row = warp_m * 64 + mt * 16 + a_row_off;
                uint32_t off = SWZ64(row * 64 + ks * 32 + a_byte_off);
                LDM_X4(ah[mt][0], ah[mt][1], ah[mt][2], ah[mt][3], st + off);
                LDM_X4(al[mt][0], al[mt][1], al[mt][2], al[mt][3], st + 8192 + off);
            }
            #pragma unroll
            for (int ng = 0; ng < 4; ng++) {
                int row = warp_n * 64 + ng * 16 + b_row_off;
                uint32_t off = SWZ64(row * 64 + ks * 32 + b_byte_off);
                uint32_t bh[4], bl[4];
                LDM_X4(bh[0], bh[1], bh[2], bh[3], st + 16384 + off);
                LDM_X4(bl[0], bl[1], bl[2], bl[3], st + 32768 + off);
                #pragma unroll
                for (int mt = 0; mt < 4; mt++) {
                    int nt0 = 2 * ng;
                    MMA_BF16(acc[mt][nt0], ah[mt][0], ah[mt][1], ah[mt][2], ah[mt][3], bh[0], bh[1]);
                    MMA_BF16(acc[mt][nt0], al[mt][0], al[mt][1], al[mt][2], al[mt][3], bh[0], bh[1]);
                    MMA_BF16(acc[mt][nt0], ah[mt][0], ah[mt][1], ah[mt][2], ah[mt][3], bl[0], bl[1]);
                    MMA_BF16(acc[mt][nt0 + 1], ah[mt][0], ah[mt][1], ah[mt][2], ah[mt][3], bh[2], bh[3]);
                    MMA_BF16(acc[mt][nt0 + 1], al[mt][0], al[mt][1], al[mt][2], al[mt][3], bh[2], bh[3]);
                    MMA_BF16(acc[mt][nt0 + 1], ah[mt][0], ah[mt][1], ah[mt][2], ah[mt][3], bl[2], bl[3]);
                }
            }
        }
    }

    // ---------------- epilogue ----------------
    int gid = lane >> 2;
    int tig = lane & 3;
    #pragma unroll
    for (int mt = 0; mt < 4; mt++) {
        int m0 = bm + warp_m * 64 + mt * 16 + gid;
        #pragma unroll
        for (int nt = 0; nt < 8; nt++) {
            int n0 = bn + warp_n * 64 + nt * 8 + tig * 2;
            float* ac = acc[mt][nt];
            #pragma unroll
            for (int half = 0; half < 2; half++) {
                int m = m0 + half * 8;
                float v0 = ac[half * 2], v1 = ac[half * 2 + 1];
                if (EPI == 0) {
                    if (n0 < 3 * C_) {
                        float2 w; w.x = v0; w.y = v1;
                        *(float2*)&Cout[(size_t)m * N + n0] = w;
                    } else {
                        int e = n0 - 3 * C_;
                        float g0 = 0.5f * v0 * (1.0f + erff(v0 * 0.70710678118654752f));
                        float g1 = 0.5f * v1 * (1.0f + erff(v1 * 0.70710678118654752f));
                        __nv_bfloat16 h0 = __float2bfloat16(g0);
                        __nv_bfloat16 h1 = __float2bfloat16(g1);
                        __nv_bfloat16 l0 = __float2bfloat16(g0 - __bfloat162float(h0));
                        __nv_bfloat16 l1 = __float2bfloat16(g1 - __bfloat162float(h1));
                        size_t ob = (size_t)m * 4096 + e;
                        *(__nv_bfloat162*)(osplit + ob)        = __nv_bfloat162(h0, h1);
                        *(__nv_bfloat162*)(osplit + ob + 2048) = __nv_bfloat162(l0, l1);
                    }
                } else if (EPI == 1) {
                    float z0 = v0 + bias[n0], z1 = v1 + bias[n0 + 1];
                    float w0 = (z0 / (1.f + expf(-z0))) * aux0[(size_t)m * 1024 + n0];
                    float w1 = (z1 / (1.f + expf(-z1))) * aux0[(size_t)m * 1024 + n0 + 1];
                    __nv_bfloat16 h0 = __float2bfloat16(w0);
                    __nv_bfloat16 h1 = __float2bfloat16(w1);
                    __nv_bfloat16 l0 = __float2bfloat16(w0 - __bfloat162float(h0));
                    __nv_bfloat16 l1 = __float2bfloat16(w1 - __bfloat162float(h1));
                    size_t ob = (size_t)m * 2048 + n0;
                    *(__nv_bfloat162*)(osplit + ob)        = __nv_bfloat162(h0, h1);
                    *(__nv_bfloat162*)(osplit + ob + 1024) = __nv_bfloat162(l0, l1);
                } else {
                    size_t o = (size_t)m * N + n0;
                    if (EPI == 2) { v0 += bias[n0]; v1 += bias[n0 + 1]; }
                    else {
                        v0 += aux0[o] + aux1[o];
                        v1 += aux0[o + 1] + aux1[o + 1];
                    }
                    float2 w; w.x = v0; w.y = v1;
                    *(float2*)&Cout[o] = w;
                }
            }
        }
    }
}

// ---------------- split helper: fp32 -> [hi | lo] ----------------
__global__ void k_split(const float* __restrict__ in, __nv_bfloat16* __restrict__ out, int K) {
    int idx = blockIdx.x * 256 + threadIdx.x;
    int r = idx / K, k = idx - r * K;
    float v = in[idx];
    __nv_bfloat16 hi = __float2bfloat16(v);
    __nv_bfloat16 lo = __float2bfloat16(v - __bfloat162float(hi));
    size_t b = (size_t)r * 2 * K + k;
    out[b] = hi;
    out[b + K] = lo;
}

// ---------------- K1: RMSNorm -> split A ----------------
__global__ void k_rmsnorm(const float* __restrict__ x, const float* __restrict__ rms_w) {
    int n = blockIdx.x;
    const float* xr = x + (size_t)n * C_;
    __shared__ float red[256];
    float s = 0.f;
    for (int c = threadIdx.x; c < C_; c += 256) { float v = xr[c]; s += v * v; }
    red[threadIdx.x] = s; __syncthreads();
    for (int o = 128; o > 0; o >>= 1) {
        if (threadIdx.x < o) red[threadIdx.x] += red[threadIdx.x + o];
        __syncthreads();
    }
    float nrm = sqrtf(red[0]) * 0.03125f;
    float inv = 1.0f / fmaxf(nrm, 1e-8f);
    size_t ob = (size_t)n * 2048;
    for (int c = threadIdx.x; c < C_; c += 256) {
        float v = xr[c] * inv * rms_w[c];
        __nv_bfloat16 hi = __float2bfloat16(v);
        __nv_bfloat16 lo = __float2bfloat16(v - __bfloat162float(hi));
        g_a_qkv[ob + c] = hi;
        g_a_qkv[ob + 1024 + c] = lo;
    }
}

// ---------------- K3: xPos rotary (one thread serves both batches) ----------------
__global__ void k_xpos() {
    int idx = blockIdx.x * 256 + threadIdx.x;        // over T_*512
    int t = idx >> 9;
    int j = idx & 511;
    float invf  = powf(10000.0f, -(float)j / 512.0f);
    float theta = (float)t * invf;
    float sn, cs;
    sincosf(theta, &sn, &cs);
    float svec  = (2.0f * (float)j + 0.4f * 1024.0f) / (1.4f * 1024.0f);
    float pw    = ((float)t - 1024.0f) * (1.0f / 512.0f);
    float scale = powf(svec, pw);
    float cq = cs * scale, sq = sn * scale;
    float ck = cs / scale, sk = sn / scale;
    #pragma unroll
    for (int b = 0; b < 2; b++) {
        float* q = g_qkvff + (size_t)(b * T_ + t) * C5 + 2 * j;
        float* k = q + C_;
        float q0 = q[0], q1 = q[1];
        q[0] = q0 * cq - q1 * sq;  q[1] = q1 * cq + q0 * sq;
        float k0 = k[0], k1 = k[1];
        k[0] = k0 * ck - k1 * sk;  k[1] = k1 * ck + k0 * sk;
    }
}

// ---------------- K4: chunk KV summaries ----------------
__global__ void k_chunk_kv() {
    int blk = blockIdx.x;
    int bh = blk / NC, c = blk % NC;
    int b = bh / H_, h = bh % H_;
    float gamma = 1.0f - exp2f(-5.0f - (float)h);
    __shared__ float Ks[64 * 65], Vs[64 * 64], dec[64];
    if (threadIdx.x < 64) dec[threadIdx.x] = powf(gamma, (float)(HD - threadIdx.x));
    __syncthreads();
    for (int i = threadIdx.x; i < HD * HD; i += 256) {
        int j = i >> 6, d = i & 63;
        size_t base = (size_t)(b * T_ + c * HD + j) * C5 + h * HD + d;
        Ks[j * 65 + d] = g_qkvff[base + C_] * dec[j];
        Vs[j * 64 + d] = g_qkvff[base + 2 * C_];
    }
    __syncthreads();
    float* Wout = g_W + ((size_t)bh * NC + c) * HD * HD;
    for (int p = threadIdx.x; p < 1024; p += 256) {
        int d = p >> 4, e0 = (p & 15) << 2;
        float s0 = 0, s1 = 0, s2 = 0, s3 = 0;
        #pragma unroll 8
        for (int j = 0; j < 64; j++) {
            float kd = Ks[j * 65 + d];
            float4 v4 = *(const float4*)&Vs[j * 64 + e0];
            s0 += kd * v4.x; s1 += kd * v4.y; s2 += kd * v4.z; s3 += kd * v4.w;
        }
        float4 r; r.x = s0; r.y = s1; r.z = s2; r.w = s3;
        *(float4*)&Wout[d * 64 + e0] = r;
    }
}

// ---------------- K5: state scan ----------------
__global__ void k_scan() {
    int bh = blockIdx.x;
    int h = bh % H_;
    float gamma = 1.0f - exp2f(-5.0f - (float)h);
    float g64 = powf(gamma, 64.0f);
    float st[16];
    #pragma unroll
    for (int r = 0; r < 16; r++) st[r] = 0.f;
    size_t base0 = (size_t)bh * NC * 4096;
    for (int c = 0; c < NC; c++) {
        size_t base = base0 + (size_t)c * 4096;
        #pragma unroll
        for (int r = 0; r < 16; r++) {
            int i = threadIdx.x + r * 256;
            g_S[base + i] = st[r];
            st[r] = st[r] * g64 + g_W[base + i];
        }
    }
}

// ---------------- K6: per-chunk attention + fused GroupNorm ----------------
__global__ void k_chunk_attn(const float* __restrict__ gn_w, const float* __restrict__ gn_b) {
    extern __shared__ float sm[];
    float* Qs   = sm;              // 64*65
    float* Kt   = Qs + 64 * 65;    // 64*68 (d-major)
    float* Vs   = Kt + 64 * 68;    // 64*64
    float* Ss   = Vs + 64 * 64;    // 64*64
    float* As   = Ss + 64 * 64;    // 64*68
    float* gpow = As + 64 * 68;    // 64
    int blk = blockIdx.x;
    int bh = blk / NC, c = blk % NC;
    int b = bh / H_, h = bh % H_;
    float gamma = 1.0f - exp2f(-5.0f - (float)h);
    if (threadIdx.x < 64) gpow[threadIdx.x] = powf(gamma, (float)threadIdx.x);
    for (int i = threadIdx.x; i < 4096; i += 256) {
        int j = i >> 6, d = i & 63;
        size_t base = (size_t)(b * T_ + c * HD + j) * C5 + h * HD + d;
        Qs[j * 65 + d] = g_qkvff[base];
        Kt[d * 68 + j] = g_qkvff[base + C_];
        Vs[j * 64 + d] = g_qkvff[base + 2 * C_];
        Ss[i] = g_S[((size_t)bh * NC + c) * 4096 + i];
    }
    __syncthreads();
    for (int p = threadIdx.x; p < 1024; p += 256) {
        int i = p >> 4, j0 = (p & 15) << 2;
        float s0 = 0, s1 = 0, s2 = 0, s3 = 0;
        #pragma unroll 8
        for (int d = 0; d < 64; d++) {
            float q = Qs[i * 65 + d];
            float4 k4 = *(const float4*)&Kt[d * 68 + j0];
            s0 += q * k4.x; s1 += q * k4.y; s2 += q * k4.z; s3 += q * k4.w;
        }
        float4 r;
        r.x = (j0     <= i) ? s0 * gpow[i - j0]     : 0.f;
        r.y = (j0 + 1 <= i) ? s1 * gpow[i - j0 - 1] : 0.f;
        r.z = (j0 + 2 <= i) ? s2 * gpow[i - j0 - 2] : 0.f;
        r.w = (j0 + 3 <= i) ? s3 * gpow[i - j0 - 3] : 0.f;
        *(float4*)&As[i * 68 + j0] = r;
    }
    __syncthreads();
    for (int p = threadIdx.x; p < 1024; p += 256) {
        int i = p >> 4, e0 = (p & 15) << 2;
        float a0 = 0, a1 = 0, a2 = 0, a3 = 0;
        float c0 = 0, c1 = 0, c2 = 0, c3 = 0;
        #pragma unroll 8
        for (int jj = 0; jj < 64; jj++) {
            float av = As[i * 68 + jj];
            float qv = Qs[i * 65 + jj];
            float4 v4 = *(const float4*)&Vs[jj * 64 + e0];
            float4 s4 = *(const float4*)&Ss[jj * 64 + e0];
            a0 += av * v4.x; a1 += av * v4.y; a2 += av * v4.z; a3 += av * v4.w;
            c0 += qv * s4.x; c1 += qv * s4.y; c2 += qv * s4.z; c3 += qv * s4.w;
        }
        float gi = gpow[i];
        float y0 = (a0 + gi * c0) * 0.125f;
        float y1 = (a1 + gi * c1) * 0.125f;
        float y2 = (a2 + gi * c2) * 0.125f;
        float y3 = (a3 + gi * c3) * 0.125f;
        float sum = y0 + y1 + y2 + y3;
        float sq  = y0 * y0 + y1 * y1 + y2 * y2 + y3 * y3;
        #pragma unroll
        for (int o = 8; o >= 1; o >>= 1) {
            sum += __shfl_xor_sync(~0u, sum, o);
            sq  += __shfl_xor_sync(~0u, sq, o);
        }
        float mu  = sum * (1.0f / 64.0f);
        float var = sq * (1.0f / 64.0f) - mu * mu;
        float inv = rsqrtf(var + 1e-5f);
        int cb = h * 64 + e0;
        float4 o4;
        o4.x = (y0 - mu) * inv * gn_w[cb]     + gn_b[cb];
        o4.y = (y1 - mu) * inv * gn_w[cb + 1] + gn_b[cb + 1];
        o4.z = (y2 - mu) * inv * gn_w[cb + 2] + gn_b[cb + 2];
        o4.w = (y3 - mu) * inv * gn_w[cb + 3] + gn_b[cb + 3];
        *(float4*)&g_y[(size_t)(b * T_ + c * HD + i) * C_ + cb] = o4;
    }
}

// ---------------- launch ----------------
extern "C" void kernel_launch(void* const* d_in, const int* in_sizes, int n_in,
                              void* d_out, int out_size) {
    const float* x       = (const float*)d_in[0];
    const float* w_qkvff = (const float*)d_in[1];
    const float* w_gated = (const float*)d_in[2];
    const float* b_gated = (const float*)d_in[3];
    const float* w_proj  = (const float*)d_in[4];
    const float* b_proj  = (const float*)d_in[5];
    const float* gn_w    = (const float*)d_in[6];
    const float* gn_b    = (const float*)d_in[7];
    const float* w_ff    = (const float*)d_in[8];
    const float* rms_w   = (const float*)d_in[9];
    float* out = (float*)d_out;

    float *p_qkvff, *p_y, *p_yp;
    __nv_bfloat16 *p_a_qkv, *p_b_qkv, *p_a_x, *p_b_gat, *p_a_prj, *p_b_prj, *p_a_ff, *p_b_ff;
    cudaGetSymbolAddress((void**)&p_qkvff, g_qkvff);
    cudaGetSymbolAddress((void**)&p_y,     g_y);
    cudaGetSymbolAddress((void**)&p_yp,    g_yp);
    cudaGetSymbolAddress((void**)&p_a_qkv, g_a_qkv);
    cudaGetSymbolAddress((void**)&p_b_qkv, g_b_qkv);
    cudaGetSymbolAddress((void**)&p_a_x,   g_a_x);
    cudaGetSymbolAddress((void**)&p_b_gat, g_b_gat);
    cudaGetSymbolAddress((void**)&p_a_prj, g_a_prj);
    cudaGetSymbolAddress((void**)&p_b_prj, g_b_prj);
    cudaGetSymbolAddress((void**)&p_a_ff,  g_a_ff);
    cudaGetSymbolAddress((void**)&p_b_ff,  g_b_ff);

    const int SMEM = 1024 + 3 * 49152;               // 148480
    const int ATTN_SMEM = (64*65 + 64*68 + 64*64 + 64*64 + 64*68 + 64) * 4;
    cudaFuncSetAttribute(mma_gemm<0>, cudaFuncAttributeMaxDynamicSharedMemorySize, SMEM);
    cudaFuncSetAttribute(mma_gemm<1>, cudaFuncAttributeMaxDynamicSharedMemorySize, SMEM);
    cudaFuncSetAttribute(mma_gemm<2>, cudaFuncAttributeMaxDynamicSharedMemorySize, SMEM);
    cudaFuncSetAttribute(mma_gemm<3>, cudaFuncAttributeMaxDynamicSharedMemorySize, SMEM);
    cudaFuncSetAttribute(k_chunk_attn, cudaFuncAttributeMaxDynamicSharedMemorySize, ATTN_SMEM);

    // weight + x splits
    k_split<<<(C5 * C_) / 256, 256>>>(w_qkvff, p_b_qkv, C_);
    k_split<<<(C_ * C_) / 256, 256>>>(w_gated, p_b_gat, C_);
    k_split<<<(C_ * C_) / 256, 256>>>(w_proj,  p_b_prj, C_);
    k_split<<<(C_ * 2 * C_) / 256, 256>>>(w_ff, p_b_ff, 2 * C_);
    k_split<<<(BT * C_) / 256, 256>>>(x, p_a_x, C_);

    // 1. RMSNorm (-> split A)
    k_rmsnorm<<<BT, 256>>>(x, rms_w);
    // 2. qkvff GEMM (q,k,v fp32; ff -> fused gelu+split)
    mma_gemm<0><<<dim3(C5 / 256, BT / 128), 256, SMEM>>>(
        p_a_qkv, p_b_qkv, C_, C5, p_qkvff, nullptr, nullptr, nullptr, p_a_ff);
    // 3. xPos
    k_xpos<<<(T_ * 512) / 256, 256>>>();
    // 4-6. chunked retention (+ fused GN)
    k_chunk_kv<<<BH * NC, 256>>>();
    k_scan<<<BH, 256>>>();
    k_chunk_attn<<<BH * NC, 256, ATTN_SMEM>>>(gn_w, gn_b);
    // 7. gate GEMM: silu(x @ w_gated^T + b) * y -> split for proj
    mma_gemm<1><<<dim3(C_ / 256, BT / 128), 256, SMEM>>>(
        p_a_x, p_b_gat, C_, C_, nullptr, b_gated, p_y, nullptr, p_a_prj);
    // 8. proj GEMM
    mma_gemm<2><<<dim3(C_ / 256, BT / 128), 256, SMEM>>>(
        p_a_prj, p_b_prj, C_, C_, p_yp, b_proj, nullptr, nullptr, nullptr);
    // 9. ff GEMM + residuals: out = gelu(ff) @ w_ff^T + x + yp
    mma_gemm<3><<<dim3(C_ / 256, BT / 128), 256, SMEM>>>(
        p_a_ff, p_b_ff, 2 * C_, C_, out, nullptr, x, p_yp, nullptr);
}